// round 2
// baseline (speedup 1.0000x reference)
#include <cuda_runtime.h>
#include <cuda_bf16.h>
#include <math.h>

#define NN 50000
#define EE 800000
#define EMB 64
#define HID 128
#define CIN1 67   // EMB + 3

// ---------------- scratch (device globals; no allocation allowed) ----------------
__device__ float g_deg[NN];
__device__ float g_dinv[NN];
__device__ int   g_cnt[NN];
__device__ int   g_off[NN + 1];
__device__ int   g_cur[NN];
__device__ int   g_srcs[EE];
__device__ float g_wsrt[EE];

__device__ float g_z[NN * EMB];     // state z
__device__ float g_h[NN * HID];     // tag output (relu'd)
__device__ float g_b0[NN * HID];    // hop ping
__device__ float g_b1[NN * HID];    // hop pong
__device__ float g_acc[NN * HID];   // gemm accumulator

__device__ __forceinline__ float gelu_exact(float x) {
    return 0.5f * x * (1.0f + erff(x * 0.70710678118654752f));
}

// ---------------- setup kernels ----------------
__global__ void k_zero() {
    int i = blockIdx.x * blockDim.x + threadIdx.x;
    if (i < NN) { g_deg[i] = 0.f; g_cnt[i] = 0; }
}

__global__ void k_hist(const int* __restrict__ col, const float* __restrict__ ea) {
    int e = blockIdx.x * blockDim.x + threadIdx.x;
    if (e < EE) {
        int c = col[e];
        atomicAdd(&g_deg[c], ea[e]);
        atomicAdd(&g_cnt[c], 1);
    }
}

__global__ void k_dinv() {
    int i = blockIdx.x * blockDim.x + threadIdx.x;
    if (i < NN) {
        float d = g_deg[i];
        g_dinv[i] = (d > 0.f) ? rsqrtf(d) : 0.f;
    }
}

// single-block scan over g_cnt -> exclusive prefix in g_off
__global__ void k_scan() {
    __shared__ int sh[1024];
    int tid = threadIdx.x;
    int carry = 0;
    for (int base = 0; base < NN; base += 1024) {
        int i = base + tid;
        int v = (i < NN) ? g_cnt[i] : 0;
        sh[tid] = v;
        __syncthreads();
        for (int ofs = 1; ofs < 1024; ofs <<= 1) {
            int t = (tid >= ofs) ? sh[tid - ofs] : 0;
            __syncthreads();
            sh[tid] += t;
            __syncthreads();
        }
        if (i < NN) g_off[i] = carry + sh[tid] - v;
        carry += sh[1023];
        __syncthreads();
    }
    if (tid == 0) g_off[NN] = carry;
}

__global__ void k_cursor() {
    int i = blockIdx.x * blockDim.x + threadIdx.x;
    if (i < NN) g_cur[i] = g_off[i];
}

__global__ void k_scatter(const int* __restrict__ row, const int* __restrict__ col,
                          const float* __restrict__ ea) {
    int e = blockIdx.x * blockDim.x + threadIdx.x;
    if (e < EE) {
        int r = row[e], c = col[e];
        int p = atomicAdd(&g_cur[c], 1);
        g_srcs[p] = r;
        g_wsrt[p] = g_dinv[r] * ea[e] * g_dinv[c];
    }
}

// ---------------- up MLP: z0 = gelu(x@W1+b1)@W2+b2 ----------------
__global__ __launch_bounds__(256) void k_up(const float* __restrict__ x,
                                            const float* __restrict__ w1, const float* __restrict__ b1,
                                            const float* __restrict__ w2, const float* __restrict__ b2) {
    __shared__ float sw2[64 * 64];
    __shared__ float hid[4][64];
    int tid = threadIdx.x;
#pragma unroll
    for (int i = 0; i < 16; i++) sw2[tid * 16 + i] = w2[tid * 16 + i];
    int local = tid >> 6;            // 0..3
    int c = tid & 63;
    int node = blockIdx.x * 4 + local;
    float h = 0.f;
    if (node < NN) {
        h = b1[c];
#pragma unroll
        for (int i = 0; i < 4; i++) h += x[node * 4 + i] * w1[i * 64 + c];
        h = gelu_exact(h);
    }
    hid[local][c] = h;
    __syncthreads();
    if (node < NN) {
        float o = b2[c];
#pragma unroll
        for (int j = 0; j < 64; j++) o += hid[local][j] * sw2[j * 64 + c];
        g_z[node * 64 + c] = o;
    }
}

// ---------------- concat: b0[n,0:64]=z, b0[n,64:67]=pos ----------------
__global__ void k_concat(const float* __restrict__ pos) {
    int i = blockIdx.x * blockDim.x + threadIdx.x;
    if (i < NN * CIN1) {
        int n = i / CIN1;
        int c = i - n * CIN1;
        g_b0[i] = (c < 64) ? g_z[n * 64 + c] : pos[n * 3 + (c - 64)];
    }
}

// ---------------- propagation: out[j] = sum_{e: col=j} w_e * in[src_e]  (CSR) --------
template <int C>
__global__ __launch_bounds__(256) void k_prop(float* __restrict__ outB, const float* __restrict__ inB) {
    int wrp = threadIdx.x >> 5, lane = threadIdx.x & 31;
    int j = blockIdx.x * 8 + wrp;
    if (j >= NN) return;
    constexpr int CC = (C + 31) / 32;
    float acc[CC];
#pragma unroll
    for (int cc = 0; cc < CC; cc++) acc[cc] = 0.f;
    int beg = g_off[j], end = g_off[j + 1];
    for (int e = beg; e < end; e++) {
        int s = g_srcs[e];
        float wt = g_wsrt[e];
        const float* p = inB + s * C;
#pragma unroll
        for (int cc = 0; cc < CC; cc++) {
            int c = cc * 32 + lane;
            if ((C % 32 == 0) || c < C) acc[cc] += wt * __ldg(&p[c]);
        }
    }
#pragma unroll
    for (int cc = 0; cc < CC; cc++) {
        int c = cc * 32 + lane;
        if ((C % 32 == 0) || c < C) outB[j * C + c] = acc[cc];
    }
}

// ---------------- GEMM: out[N,COUT] (+)= A[N,Cin] @ W[Cin,COUT] ----------------
template <int COUT, bool INIT>
__global__ __launch_bounds__(256) void k_gemm(float* __restrict__ outp, const float* __restrict__ A,
                                              const float* __restrict__ W, int Cin) {
    constexpr int CPT = COUT / 32;            // couts per lane (4 or 2)
    __shared__ float As[16][64];
    __shared__ float Ws[16][COUT];
    int tid = threadIdx.x, lane = tid & 31, wrp = tid >> 5;
    int row0 = blockIdx.x * 64;
    int rb = wrp * 8;
    float acc[8][CPT];
#pragma unroll
    for (int r = 0; r < 8; r++)
#pragma unroll
        for (int c = 0; c < CPT; c++) acc[r][c] = 0.f;

    int lr = tid >> 2;          // 0..63, A row within tile
    int lk = (tid & 3) * 4;     // 0,4,8,12
    int grow = row0 + lr;
    const float* arow = A + grow * Cin;

    for (int k0 = 0; k0 < Cin; k0 += 16) {
#pragma unroll
        for (int i = 0; i < 4; i++) {
            int kk = lk + i;
            int k = k0 + kk;
            float v = 0.f;
            if (grow < NN && k < Cin) v = arow[k];
            As[kk][lr] = v;
        }
        constexpr int WE = 16 * COUT / 256;   // 8 or 4
#pragma unroll
        for (int i = 0; i < WE; i++) {
            int off = tid * WE + i;
            int kk = off / COUT, c = off - kk * COUT;
            int k = k0 + kk;
            Ws[kk][c] = (k < Cin) ? W[k * COUT + c] : 0.f;
        }
        __syncthreads();
#pragma unroll
        for (int kk = 0; kk < 16; kk++) {
            float a[8];
            float4 a0 = *(const float4*)&As[kk][rb];
            float4 a1 = *(const float4*)&As[kk][rb + 4];
            a[0] = a0.x; a[1] = a0.y; a[2] = a0.z; a[3] = a0.w;
            a[4] = a1.x; a[5] = a1.y; a[6] = a1.z; a[7] = a1.w;
            float w[CPT];
            if constexpr (CPT == 4) {
                float4 wv = *(const float4*)&Ws[kk][lane * 4];
                w[0] = wv.x; w[1] = wv.y; w[2] = wv.z; w[3] = wv.w;
            } else {
                float2 wv = *(const float2*)&Ws[kk][lane * 2];
                w[0] = wv.x; w[1] = wv.y;
            }
#pragma unroll
            for (int r = 0; r < 8; r++)
#pragma unroll
                for (int c = 0; c < CPT; c++)
                    acc[r][c] = fmaf(a[r], w[c], acc[r][c]);
        }
        __syncthreads();
    }

#pragma unroll
    for (int r = 0; r < 8; r++) {
        int row = row0 + rb + r;
        if (row < NN) {
            float* p = outp + row * COUT + lane * CPT;
            if constexpr (CPT == 4) {
                float4 v;
                if (!INIT) {
                    float4 o = *(const float4*)p;
                    v.x = o.x + acc[r][0]; v.y = o.y + acc[r][1];
                    v.z = o.z + acc[r][2]; v.w = o.w + acc[r][3];
                } else {
                    v.x = acc[r][0]; v.y = acc[r][1]; v.z = acc[r][2]; v.w = acc[r][3];
                }
                *(float4*)p = v;
            } else {
                float2 v;
                if (!INIT) {
                    float2 o = *(const float2*)p;
                    v.x = o.x + acc[r][0]; v.y = o.y + acc[r][1];
                } else {
                    v.x = acc[r][0]; v.y = acc[r][1];
                }
                *(float2*)p = v;
            }
        }
    }
}

// ---------------- bias + relu ----------------
__global__ void k_bias_relu(const float* __restrict__ b) {
    int i = blockIdx.x * blockDim.x + threadIdx.x;
    if (i < NN * HID) {
        int c = i & (HID - 1);
        g_h[i] = fmaxf(g_acc[i] + b[c], 0.f);
    }
}

// ---------------- bias + log_softmax over 64 channels -> g_z ----------------
__global__ __launch_bounds__(256) void k_bias_logsm(const float* __restrict__ b) {
    int wrp = threadIdx.x >> 5, lane = threadIdx.x & 31;
    int j = blockIdx.x * 8 + wrp;
    if (j >= NN) return;
    float v0 = g_acc[j * 64 + lane] + b[lane];
    float v1 = g_acc[j * 64 + 32 + lane] + b[32 + lane];
    float m = fmaxf(v0, v1);
#pragma unroll
    for (int o = 16; o; o >>= 1) m = fmaxf(m, __shfl_xor_sync(0xffffffffu, m, o));
    float s = expf(v0 - m) + expf(v1 - m);
#pragma unroll
    for (int o = 16; o; o >>= 1) s += __shfl_xor_sync(0xffffffffu, s, o);
    float l = m + logf(s);
    g_z[j * 64 + lane] = v0 - l;
    g_z[j * 64 + 32 + lane] = v1 - l;
}

// ---------------- down MLP + output write ----------------
__global__ __launch_bounds__(256) void k_down(float* __restrict__ out,
                                              const float* __restrict__ w1, const float* __restrict__ b1,
                                              const float* __restrict__ w2, const float* __restrict__ b2) {
    int wrp = threadIdx.x >> 5, lane = threadIdx.x & 31;
    int j = blockIdx.x * 8 + wrp;
    if (j >= NN) return;
    float z0 = g_z[j * 64 + lane];
    float z1 = g_z[j * 64 + 32 + lane];
    // z_star copy (second output)
    out[NN + j * 64 + lane] = z0;
    out[NN + j * 64 + 32 + lane] = z1;
    float d = z0 * w1[lane] + z1 * w1[32 + lane];
#pragma unroll
    for (int o = 16; o; o >>= 1) d += __shfl_xor_sync(0xffffffffu, d, o);
    if (lane == 0) out[j] = gelu_exact(d + b1[0]) * w2[0] + b2[0];
}

// ---------------- host orchestration ----------------
extern "C" void kernel_launch(void* const* d_in, const int* in_sizes, int n_in,
                              void* d_out, int out_size) {
    const float* x      = (const float*)d_in[0];
    const float* pos    = (const float*)d_in[1];
    const float* ea     = (const float*)d_in[2];
    const float* up_w1  = (const float*)d_in[3];
    const float* up_b1  = (const float*)d_in[4];
    const float* up_w2  = (const float*)d_in[5];
    const float* up_b2  = (const float*)d_in[6];
    const float* c1_w   = (const float*)d_in[7];
    const float* c1_b   = (const float*)d_in[8];
    const float* c2_w   = (const float*)d_in[9];
    const float* c2_b   = (const float*)d_in[10];
    const float* c3_w   = (const float*)d_in[11];
    const float* c3_b   = (const float*)d_in[12];
    const float* dw1    = (const float*)d_in[13];
    const float* db1    = (const float*)d_in[14];
    const float* dw2    = (const float*)d_in[15];
    const float* db2    = (const float*)d_in[16];
    const int*   ei     = (const int*)d_in[17];
    const int* row = ei;
    const int* col = ei + EE;

    float *b0, *b1, *h, *acc;
    cudaGetSymbolAddress((void**)&b0,  g_b0);
    cudaGetSymbolAddress((void**)&b1,  g_b1);
    cudaGetSymbolAddress((void**)&h,   g_h);
    cudaGetSymbolAddress((void**)&acc, g_acc);

    const int GN  = (NN + 255) / 256;
    const int GE  = (EE + 255) / 256;
    const int GW  = (NN + 7) / 8;        // warp-per-node grids
    const int GG  = (NN + 63) / 64;      // gemm grids
    const int GEL = (NN * HID + 255) / 256;
    const int GCC = (NN * CIN1 + 255) / 256;

    // --- graph setup (CSR by destination, gcn norm) ---
    k_zero<<<GN, 256>>>();
    k_hist<<<GE, 256>>>(col, ea);
    k_dinv<<<GN, 256>>>();
    k_scan<<<1, 1024>>>();
    k_cursor<<<GN, 256>>>();
    k_scatter<<<GE, 256>>>(row, col, ea);

    // --- up MLP -> z0 ---
    k_up<<<(NN + 3) / 4, 256>>>(x, up_w1, up_b1, up_w2, up_b2);

    // --- 21 gnn applications (20 fixed-point + 1 phantom) ---
    for (int it = 0; it < 21; it++) {
        // tag1: Cin=67 -> 128
        k_concat<<<GCC, 256>>>(pos);
        k_gemm<128, true><<<GG, 256>>>(acc, b0, c1_w, CIN1);
        {
            float* srcs[4] = {b0, b1, b0, b1};
            for (int k = 1; k <= 3; k++) {
                float* s = srcs[k - 1];
                float* d = srcs[k];
                k_prop<CIN1><<<GW, 256>>>(d, s);
                k_gemm<128, false><<<GG, 256>>>(acc, d, c1_w + k * CIN1 * 128, CIN1);
            }
        }
        k_bias_relu<<<GEL, 256>>>(c1_b);

        // tag2: 128 -> 128
        k_gemm<128, true><<<GG, 256>>>(acc, h, c2_w, HID);
        {
            float* bufs[4] = {h, b0, b1, b0};
            for (int k = 1; k <= 3; k++) {
                k_prop<HID><<<GW, 256>>>(bufs[k], bufs[k - 1]);
                k_gemm<128, false><<<GG, 256>>>(acc, bufs[k], c2_w + k * HID * 128, HID);
            }
        }
        k_bias_relu<<<GEL, 256>>>(c2_b);

        // tag3: 128 -> 64, then log_softmax -> z
        k_gemm<64, true><<<GG, 256>>>(acc, h, c3_w, HID);
        {
            float* bufs[4] = {h, b0, b1, b0};
            for (int k = 1; k <= 3; k++) {
                k_prop<HID><<<GW, 256>>>(bufs[k], bufs[k - 1]);
                k_gemm<64, false><<<GG, 256>>>(acc, bufs[k], c3_w + k * HID * 64, HID);
            }
        }
        k_bias_logsm<<<GW, 256>>>(c3_b);
    }

    // --- down MLP + write (out, z_star) ---
    k_down<<<GW, 256>>>((float*)d_out, dw1, db1, dw2, db2);

    (void)in_sizes; (void)n_in; (void)out_size;
}